// round 13
// baseline (speedup 1.0000x reference)
#include <cuda_runtime.h>
#include <cuda_fp16.h>
#include <cstdint>
#include <cstddef>

// ============================ problem constants =============================
namespace cfg {
constexpr int B  = 512;
constexpr int C  = 200;
constexpr int E  = 128;
constexpr int CV = 384;
constexpr int F  = 384;                 // K dim (3E)
constexpr int ROWS = B * C;             // 102400
constexpr int MT = 64;                  // rows per CTA tile
constexpr int NTILES = ROWS / MT;       // 1600
constexpr int NTH = 256;                // 8 warps: 2 (M) x 4 (N)

constexpr int APAD = 392;               // A row: 384 + 8 fp16 -> 784 B
constexpr int BPAD = 40;                // B row: 32 + 8 fp16  -> 80 B

// dynamic smem layout (bytes)
constexpr uint32_t A_OFF = 0;            // [64][392] fp16 = 50176
constexpr uint32_t B0    = 50176;        // [128][40] fp16 = 10240
constexpr uint32_t B1    = 60416;        // 10240
constexpr uint32_t IDX   = 70656;        // 192 ints = 768
constexpr uint32_t RED   = 71424;        // 3 x 64 floats = 768
constexpr uint32_t SMEM_BYTES = 72192;   // x3 CTAs = 216576 <= 227KB SM budget
constexpr int NCHUNK = 36;               // 3 nt x 12 kc
}

// ===================== device scratch (no runtime alloc) ====================
__device__ __half    g_Wf16[cfg::CV * cfg::F];       // W fp16, [v][k] row-major
__device__ uint32_t  g_h2[(size_t)cfg::ROWS * cfg::CV / 2];  // h as half2 pairs
__device__ float     g_scores[cfg::ROWS];
__device__ int       g_tileflag[cfg::NTILES];        // tile-done flags

// ============================== PTX helpers =================================
__device__ __forceinline__ uint32_t smem_u32(const void* p) {
    uint32_t a;
    asm("{ .reg .u64 t; cvta.to.shared.u64 t, %1; cvt.u32.u64 %0, t; }" : "=r"(a) : "l"(p));
    return a;
}
__device__ __forceinline__ void ldsm_x4(uint32_t (&r)[4], uint32_t addr) {
    asm volatile("ldmatrix.sync.aligned.m8n8.x4.shared.b16 {%0,%1,%2,%3}, [%4];"
                 : "=r"(r[0]), "=r"(r[1]), "=r"(r[2]), "=r"(r[3]) : "r"(addr));
}
__device__ __forceinline__ void mma_f16(float (&d)[4], const uint32_t (&a)[4],
                                        uint32_t b0, uint32_t b1) {
    asm volatile(
        "mma.sync.aligned.m16n8k16.row.col.f32.f16.f16.f32 "
        "{%0,%1,%2,%3}, {%4,%5,%6,%7}, {%8,%9}, {%0,%1,%2,%3};"
        : "+f"(d[0]), "+f"(d[1]), "+f"(d[2]), "+f"(d[3])
        : "r"(a[0]), "r"(a[1]), "r"(a[2]), "r"(a[3]), "r"(b0), "r"(b1));
}
__device__ __forceinline__ void cp_async16(uint32_t dst, const void* src) {
    asm volatile("cp.async.cg.shared.global [%0], [%1], 16;"
                 :: "r"(dst), "l"(src) : "memory");
}
__device__ __forceinline__ void cp_commit() {
    asm volatile("cp.async.commit_group;" ::: "memory");
}
__device__ __forceinline__ void cp_wait1() {
    asm volatile("cp.async.wait_group 1;" ::: "memory");
}
__device__ __forceinline__ uint32_t h2_bits(float lo, float hi) {
    __half2 h = __floats2half2_rn(lo, hi);
    return *(uint32_t*)&h;
}
// fast branchless tanh: MUFU.EX2 + fast divide, abs err ~1e-6
__device__ __forceinline__ float ftanh(float x) {
    x = fminf(fmaxf(x, -15.f), 15.f);
    float t = __expf(2.f * x);
    return __fdividef(t - 1.f, t + 1.f);
}

// ======= kernel 0: W fp32 -> fp16 ([v][k] row-major) + flag reset ===========
__global__ void __launch_bounds__(256)
wconv_kernel(const float* __restrict__ W) {
    int i = blockIdx.x * 256 + threadIdx.x;          // float4 id, 36864 total
    float4 x = ((const float4*)W)[i];
    ((uint2*)g_Wf16)[i] = make_uint2(h2_bits(x.x, x.y), h2_bits(x.z, x.w));
    if (i < cfg::NTILES) g_tileflag[i] = 0;          // reset deps each replay
}

// == kernel 1: gather + fp16 HMMA GEMM + tanh + h + scores + fused softmax ===
__global__ void __launch_bounds__(cfg::NTH, 3)
k1_mma_kernel(const int* __restrict__ starts,
              const int* __restrict__ paths,
              const int* __restrict__ ends,
              const float* __restrict__ node_emb,
              const float* __restrict__ path_emb,
              const float* __restrict__ avec,
              float* __restrict__ out) {
    using namespace cfg;
    extern __shared__ char smem[];
    const uint32_t sb = smem_u32(smem);
    const int tid = threadIdx.x;
    const int wid = tid >> 5, lane = tid & 31;
    const int wm = wid & 1;              // M slice (32 rows)
    const int wn = wid >> 1;             // N slice (32 cols of 128-chunk)
    const int tile = blockIdx.x;
    int* sidx = (int*)(smem + IDX);
    float* red = (float*)(smem + RED);   // [3][64]

    // ---- indices (64 rows x 3) ----
    if (tid < 192) {
        int seg = tid >> 6, r = tid & 63;
        const int* p = (seg == 0) ? starts : (seg == 1) ? paths : ends;
        sidx[tid] = p[tile * 64 + r];
    }
    __syncthreads();

    // ---- B chunk staging: [128 n][32 k] fp16 = 512 x 16B, 2 per thread ----
    auto stageB = [&](int q, uint32_t buf) {
        const int nt = q / 12, kc = q % 12;
        #pragma unroll
        for (int i = 0; i < 2; ++i) {
            int t = tid + i * 256;                   // 0..511
            int n = t >> 2, ch = t & 3;              // row, 16B chunk (8 fp16)
            const __half* src = g_Wf16 +
                ((size_t)(nt * 128 + n) * 384 + kc * 32 + ch * 8);
            cp_async16(sb + buf + (uint32_t)n * (BPAD * 2) + (uint32_t)ch * 16, src);
        }
        cp_commit();
    };
    stageB(0, B0);                                   // overlaps gather

    // ---- gather ctx rows -> fp16 into padded A (per-seg: no div/mod) ----
    #pragma unroll
    for (int seg = 0; seg < 3; ++seg) {
        const float4* src = (seg == 1) ? (const float4*)path_emb
                                       : (const float4*)node_emb;
        #pragma unroll 2
        for (int i = 0; i < 8; ++i) {
            int task = tid + i * 256;                // 0..2047
            int row = task >> 5, j = task & 31;
            int idx = sidx[seg * 64 + row];
            float4 x = __ldg(src + (size_t)idx * 32 + j);
            int k = seg * 128 + j * 4;
            *(uint2*)(smem + A_OFF + (uint32_t)row * (APAD * 2) + (uint32_t)k * 2) =
                make_uint2(h2_bits(x.x, x.y), h2_bits(x.z, x.w));
        }
    }
    __syncthreads();
    stageB(1, B1);

    // ---- ldmatrix lane addresses ----
    const uint32_t a_lane = sb + A_OFF + (uint32_t)(wm * 32 + (lane & 15)) * (APAD * 2)
                          + (uint32_t)(lane >> 4) * 16;
    const int bgrp = lane >> 3;
    const uint32_t b_lane = (uint32_t)(((bgrp & 2) << 2) + (lane & 7)) * (BPAD * 2)
                          + (uint32_t)(bgrp & 1) * 16;

    float sc[2][2] = {{0.f, 0.f}, {0.f, 0.f}};       // score partials [mi][rowhalf]
    const size_t rowbase = (size_t)tile * 64;

    for (int nt = 0; nt < 3; ++nt) {
        float acc[2][4][4];
        #pragma unroll
        for (int mi = 0; mi < 2; ++mi)
            #pragma unroll
            for (int ni = 0; ni < 4; ++ni)
                #pragma unroll
                for (int q = 0; q < 4; ++q) acc[mi][ni][q] = 0.f;

        for (int kc = 0; kc < 12; ++kc) {
            const int q = nt * 12 + kc;
            const uint32_t buf = sb + ((q & 1) ? B1 : B0);
            // One group committed per iteration (real stage or empty commit),
            // so wait_group 1 provably drains chunk q's group (R8 tail fix).
            cp_wait1();
            __syncthreads();

            #pragma unroll
            for (int s = 0; s < 2; ++s) {            // two k16 steps
                const uint32_t akoff = (uint32_t)(kc * 32 + s * 16) * 2;
                uint32_t a[2][4];
                #pragma unroll
                for (int mi = 0; mi < 2; ++mi)
                    ldsm_x4(a[mi], a_lane + mi * (16 * APAD * 2) + akoff);
                #pragma unroll
                for (int bj = 0; bj < 2; ++bj) {
                    const uint32_t bn = (uint32_t)(wn * 32 + bj * 16) * (BPAD * 2)
                                      + (uint32_t)(s * 32);
                    uint32_t r[4];
                    ldsm_x4(r, buf + b_lane + bn);
                    #pragma unroll
                    for (int mi = 0; mi < 2; ++mi) {
                        mma_f16(acc[mi][2*bj],   a[mi], r[0], r[1]);
                        mma_f16(acc[mi][2*bj+1], a[mi], r[2], r[3]);
                    }
                }
            }

            __syncthreads();                         // reads of buf done
            if (q + 2 < NCHUNK) stageB(q + 2, (q & 1) ? B1 : B0);
            else                cp_commit();         // empty group, keep depth
        }

        // ---- epilogue: fast tanh, half2 h store, score partials ----
        #pragma unroll
        for (int mi = 0; mi < 2; ++mi) {
            const int r0 = wm * 32 + mi * 16 + (lane >> 2);
            #pragma unroll
            for (int ni = 0; ni < 4; ++ni) {
                const int v0 = nt * 128 + wn * 32 + ni * 8 + (lane & 3) * 2;
                const float a0v = __ldg(avec + v0);
                const float a1v = __ldg(avec + v0 + 1);
                float h00 = ftanh(acc[mi][ni][0]);
                float h01 = ftanh(acc[mi][ni][1]);
                float h10 = ftanh(acc[mi][ni][2]);
                float h11 = ftanh(acc[mi][ni][3]);
                g_h2[(rowbase + r0) * 192 + (v0 >> 1)]     = h2_bits(h00, h01);
                g_h2[(rowbase + r0 + 8) * 192 + (v0 >> 1)] = h2_bits(h10, h11);
                sc[mi][0] += h00 * a0v + h01 * a1v;
                sc[mi][1] += h10 * a0v + h11 * a1v;
            }
        }
    }

    // ---- score reduction: quad shfl, then cross-warp over wn=0..3 ----
    #pragma unroll
    for (int mi = 0; mi < 2; ++mi)
        #pragma unroll
        for (int j = 0; j < 2; ++j) {
            float s = sc[mi][j];
            s += __shfl_xor_sync(0xFFFFFFFFu, s, 1);
            s += __shfl_xor_sync(0xFFFFFFFFu, s, 2);
            sc[mi][j] = s;
        }
    __syncthreads();
    if (wn > 0 && (lane & 3) == 0) {
        #pragma unroll
        for (int mi = 0; mi < 2; ++mi)
            #pragma unroll
            for (int j = 0; j < 2; ++j)
                red[(wn - 1) * 64 + wm * 32 + mi * 16 + j * 8 + (lane >> 2)] =
                    sc[mi][j];
    }
    __syncthreads();
    if (wn == 0 && (lane & 3) == 0) {
        #pragma unroll
        for (int mi = 0; mi < 2; ++mi)
            #pragma unroll
            for (int j = 0; j < 2; ++j) {
                int lr = wm * 32 + mi * 16 + j * 8 + (lane >> 2);
                // fixed summation order: deterministic
                g_scores[rowbase + lr] =
                    sc[mi][j] + red[lr] + red[64 + lr] + red[128 + lr];
            }
    }

    // ==================== fused softmax + weighted sum ======================
    __syncthreads();                     // h + scores for this tile complete
    if (tid == 0) {
        __threadfence();                 // publish h/scores before flag
        atomicExch(&g_tileflag[tile], 1);
    }

    // Does some batch b have its LAST tile == this tile?  (unique if so)
    int bsel = -1;
    {
        int lo = 64 * tile - 199;
        lo = (lo < 0) ? 0 : lo / 200;
        #pragma unroll
        for (int d = 0; d < 2; ++d) {
            int bb = lo + d;
            if (bb < B && ((200 * bb + 199) >> 6) == tile) bsel = bb;
        }
    }
    if (bsel < 0) return;
    const int b = bsel;
    const int t0 = (200 * b) >> 6;

    // Wait for the earlier tiles covering rows [200b, 200b+199].
    // Only strictly lower block-ids are waited on -> no deadlock under
    // bid-monotone dispatch.
    if (tid == 0) {
        for (int t = t0; t < tile; ++t)
            while (atomicAdd(&g_tileflag[t], 0) == 0) __nanosleep(64);
        __threadfence();                 // acquire: order flag -> h reads
    }
    __syncthreads();

    // smem reuse (A region dead): scs[200] attn[200] red2[32] sred[768]
    float* s2   = (float*)smem;
    float* scs  = s2;
    float* attn = s2 + 200;
    float* red2 = s2 + 400;
    float* sred = s2 + 432;
    __shared__ float s_max, s_sum;

    if (tid < C) scs[tid] = __ldcg(g_scores + (size_t)b * C + tid);
    __syncthreads();

    if (tid < 32) {
        float m = -3.4e38f;
        for (int c = tid; c < C; c += 32) m = fmaxf(m, scs[c]);
        red2[tid] = m;
    }
    __syncthreads();
    if (tid == 0) {
        float m = red2[0];
        #pragma unroll
        for (int j = 1; j < 32; ++j) m = fmaxf(m, red2[j]);
        s_max = m;
    }
    __syncthreads();
    if (tid < 32) {
        float s = 0.f;
        for (int c = tid; c < C; c += 32) s += expf(scs[c] - s_max);
        red2[tid] = s;
    }
    __syncthreads();
    if (tid == 0) {
        float s = 0.f;
        #pragma unroll
        for (int j = 0; j < 32; ++j) s += red2[j];
        s_sum = s;
    }
    __syncthreads();
    if (tid < C) attn[tid] = expf(scs[tid] - s_max) / s_sum;
    __syncthreads();

    // Weighted sum over c: rows are 96 uint2 (LDG.64). Threads 0..191:
    // vq = tid % 96 (v = 4vq..4vq+3), phase cg = tid / 96 in {0,1}; c += 2.
    if (tid < 192) {
        const int vq = tid % 96;
        const int cg = tid / 96;
        const uint2* hb = (const uint2*)g_h2 + (size_t)b * C * 96;
        float a0 = 0.f, a1 = 0.f, a2 = 0.f, a3 = 0.f;
        #pragma unroll 2
        for (int c = cg; c < C; c += 2) {
            const float w = attn[c];
            uint2 d = __ldcg(hb + (size_t)c * 96 + vq);
            __half2 p0 = *(__half2*)&d.x;
            __half2 p1 = *(__half2*)&d.y;
            float2 f0 = __half22float2(p0);
            float2 f1 = __half22float2(p1);
            a0 = fmaf(w, f0.x, a0);
            a1 = fmaf(w, f0.y, a1);
            a2 = fmaf(w, f1.x, a2);
            a3 = fmaf(w, f1.y, a3);
        }
        sred[cg * CV + vq * 4 + 0] = a0;
        sred[cg * CV + vq * 4 + 1] = a1;
        sred[cg * CV + vq * 4 + 2] = a2;
        sred[cg * CV + vq * 4 + 3] = a3;
    }
    __syncthreads();

    // final: fixed summation order (deterministic)
    if (tid < CV) {
        int v = tid;
        out[(size_t)b * CV + v] = sred[v] + sred[CV + v];
    }
    if (tid < CV - 256) {
        int v = tid + 256;
        out[(size_t)b * CV + v] = sred[v] + sred[CV + v];
    }
}

// ================================ launch =====================================
extern "C" void kernel_launch(void* const* d_in, const int* in_sizes, int n_in,
                              void* d_out, int out_size) {
    (void)in_sizes; (void)n_in; (void)out_size;
    const int*   starts   = (const int*)d_in[0];
    const int*   paths    = (const int*)d_in[1];
    const int*   ends     = (const int*)d_in[2];
    /* masks d_in[3] unused by the reference */
    const float* node_emb = (const float*)d_in[4];
    const float* path_emb = (const float*)d_in[5];
    const float* W        = (const float*)d_in[6];
    const float* avec     = (const float*)d_in[7];
    float* out = (float*)d_out;

    cudaFuncSetAttribute(k1_mma_kernel,
                         cudaFuncAttributeMaxDynamicSharedMemorySize,
                         (int)cfg::SMEM_BYTES);

    wconv_kernel<<<cfg::CV * cfg::F / 4 / 256, 256>>>(W);
    k1_mma_kernel<<<cfg::NTILES, cfg::NTH, cfg::SMEM_BYTES>>>(
        starts, paths, ends, node_emb, path_emb, avec, out);
}